// round 16
// baseline (speedup 1.0000x reference)
#include <cuda_runtime.h>
#include <cuda_bf16.h>
#include <cuda_fp16.h>
#include <cuda_fp8.h>

#define N_NODES 100000
#define N_EDGES 3200000
#define F_IN    512
#define F_HID   256
#define N_CLASS 41
#define H2P     44                            // padded h2 row (bf16)
#define SCAN_BLOCKS ((N_NODES + 255) / 256)   // 391
#define AK 40   // smem k-stride in bf16 halves (32 data + 8 pad)

// ---------------- scratch (device globals; no allocation allowed) ----------
__device__ __nv_bfloat16 g_w1t[(size_t)F_HID * F_IN];      // W1^T [n][k] bf16
__device__ __nv_bfloat16 g_w2t[(size_t)64 * F_HID];        // W2^T padded [64][256]
__device__ unsigned char g_h1f8[(size_t)N_NODES * F_HID];  // x@W1 in fp8 e4m3
__device__ __nv_bfloat16 g_a1b[(size_t)N_NODES * F_HID];   // relu(agg+self+b1) bf16
__device__ __nv_bfloat16 g_h2b[(size_t)N_NODES * H2P];     // a1 @ W2 (bf16, padded)
__device__ int   g_deg[N_NODES];
__device__ float g_dinv[N_NODES];
__device__ int   g_rowptr[N_NODES + 1];
__device__ int   g_cursor[N_NODES];
__device__ int   g_bsum[SCAN_BLOCKS];
__device__ int   g_bsumx[SCAN_BLOCKS];
__device__ int   g_csrc[N_EDGES];
__device__ int   g_is64;

// ---------------- small helpers --------------------------------------------
__device__ __forceinline__ void cp16(void* s, const void* g) {
    unsigned sa = (unsigned)__cvta_generic_to_shared(s);
    asm volatile("cp.async.cg.shared.global [%0],[%1],16;" :: "r"(sa), "l"(g));
}
__device__ __forceinline__ void cp16z(void* s, const void* g, bool pred) {
    unsigned sa = (unsigned)__cvta_generic_to_shared(s);
    int sz = pred ? 16 : 0;
    asm volatile("cp.async.cg.shared.global [%0],[%1],16,%2;" :: "r"(sa), "l"(g), "r"(sz));
}
#define CP_COMMIT() asm volatile("cp.async.commit_group;")

__device__ __forceinline__ void mma16816(float c[4], const unsigned a[4],
                                         unsigned b0, unsigned b1) {
    asm volatile(
        "mma.sync.aligned.m16n8k16.row.col.f32.bf16.bf16.f32 "
        "{%0,%1,%2,%3},{%4,%5,%6,%7},{%8,%9},{%0,%1,%2,%3};"
        : "+f"(c[0]), "+f"(c[1]), "+f"(c[2]), "+f"(c[3])
        : "r"(a[0]), "r"(a[1]), "r"(a[2]), "r"(a[3]), "r"(b0), "r"(b1));
}

__device__ __forceinline__ void ldsm_x4(unsigned& r0, unsigned& r1,
                                        unsigned& r2, unsigned& r3,
                                        const void* p) {
    unsigned addr = (unsigned)__cvta_generic_to_shared(p);
    asm volatile("ldmatrix.sync.aligned.m8n8.x4.shared.b16 {%0,%1,%2,%3},[%4];"
                 : "=r"(r0), "=r"(r1), "=r"(r2), "=r"(r3) : "r"(addr));
}

// ---------------- deg init + parallel edge-dtype detection ------------------
__global__ void k_deg_detect(const void* __restrict__ ei) {
    int i = blockIdx.x * blockDim.x + threadIdx.x;
    if (i < N_NODES) g_deg[i] = 1;
    if (blockIdx.x == 0) {
        __shared__ int s_ok;
        if (threadIdx.x == 0) s_ok = 1;
        __syncthreads();
        if (threadIdx.x < 128) {
            long long v = ((const long long*)ei)[threadIdx.x];
            if (v < 0 || v >= N_NODES) atomicAnd(&s_ok, 0);
        }
        __syncthreads();
        if (threadIdx.x == 0) g_is64 = s_ok;
    }
}

__device__ __forceinline__ void load_edge(const void* __restrict__ ei, int e,
                                          int is64, int& s, int& d) {
    if (is64) {
        const long long* p = (const long long*)ei;
        s = (int)p[e];
        d = (int)p[N_EDGES + e];
    } else {
        const int* p = (const int*)ei;
        s = p[e];
        d = p[N_EDGES + e];
    }
}

__global__ void k_count(const void* __restrict__ ei) {
    int e = blockIdx.x * blockDim.x + threadIdx.x;
    if (e >= N_EDGES) return;
    int s, d;
    load_edge(ei, e, g_is64, s, d);
    if ((unsigned)d < N_NODES) atomicAdd(&g_deg[d], 1);
}

// ---------------- CSR build -------------------------------------------------
__global__ void k_scan1() {
    __shared__ int sh[256];
    int t = threadIdx.x;
    int i = blockIdx.x * 256 + t;
    int deg = (i < N_NODES) ? g_deg[i] : 1;
    if (i < N_NODES) g_dinv[i] = rsqrtf((float)deg);
    int v = (i < N_NODES) ? (deg - 1) : 0;
    sh[t] = v;
    __syncthreads();
#pragma unroll
    for (int off = 1; off < 256; off <<= 1) {
        int add = (t >= off) ? sh[t - off] : 0;
        __syncthreads();
        sh[t] += add;
        __syncthreads();
    }
    if (i < N_NODES) g_rowptr[i] = sh[t] - v;
    if (t == 255) g_bsum[blockIdx.x] = sh[t];
}
__global__ void k_scan2() {
    __shared__ int sh[512];
    int t = threadIdx.x;
    int v = (t < SCAN_BLOCKS) ? g_bsum[t] : 0;
    sh[t] = v;
    __syncthreads();
#pragma unroll
    for (int off = 1; off < 512; off <<= 1) {
        int add = (t >= off) ? sh[t - off] : 0;
        __syncthreads();
        sh[t] += add;
        __syncthreads();
    }
    if (t < SCAN_BLOCKS) g_bsumx[t] = sh[t] - v;
}
__global__ void k_scan3() {
    int i = blockIdx.x * blockDim.x + threadIdx.x;
    if (i < N_NODES) {
        int r = g_rowptr[i] + g_bsumx[i >> 8];
        g_rowptr[i] = r;
        g_cursor[i] = r;
    }
    if (i == 0)
        g_rowptr[N_NODES] = g_bsumx[SCAN_BLOCKS - 1] + g_bsum[SCAN_BLOCKS - 1];
}
__global__ void k_fill(const void* __restrict__ ei) {
    int e = blockIdx.x * blockDim.x + threadIdx.x;
    if (e >= N_EDGES) return;
    int s, d;
    load_edge(ei, e, g_is64, s, d);
    if ((unsigned)s >= N_NODES || (unsigned)d >= N_NODES) return;
    int pos = atomicAdd(&g_cursor[d], 1);
    g_csrc[pos] = s;
}

// ---------------- weight conversions (merged) --------------------------------
__global__ void k_wt(const float* __restrict__ W1, const float* __restrict__ W2) {
    int id = blockIdx.x * blockDim.x + threadIdx.x;
    if (id < F_IN * F_HID) {
        int n = id & (F_HID - 1), k = id >> 8;
        g_w1t[(size_t)n * F_IN + k] = __float2bfloat16(W1[(size_t)k * F_HID + n]);
    } else if (id < F_IN * F_HID + 64 * F_HID) {
        int id2 = id - F_IN * F_HID;
        int n = id2 & 63, k = id2 >> 6;
        float v = (n < N_CLASS) ? W2[(size_t)k * N_CLASS + n] : 0.f;
        g_w2t[(size_t)n * F_HID + k] = __float2bfloat16(v);
    }
}

// ---------------- GEMM1: 64x128 tile, 256 thr, 3 CTAs/SM, ldmatrix ---------
// grid = (2, 1563): n-block fastest so the CTA pair sharing x rows is
// co-scheduled and the second x read hits L2.
__global__ __launch_bounds__(256, 3) void k_gemm1d(const float* __restrict__ x) {
    extern __shared__ __align__(16) __nv_bfloat16 smem[];
    __nv_bfloat16* As = smem;                  // 2 bufs x 64*AK
    __nv_bfloat16* Bs = smem + 2 * 64 * AK;    // 2 bufs x 128*AK
    int tid = threadIdx.x;
    int bn = blockIdx.x * 128;
    int bm = blockIdx.y * 64;
    int wid = tid >> 5, lane = tid & 31;
    int wm = (wid & 1) * 32, wn = (wid >> 1) * 32;   // 2(m) x 4(n) warps
    int g = lane >> 2, tg = lane & 3;

    int q = lane >> 3, rr = lane & 7;
    int a_sel = (wm + (q & 1) * 8 + rr) * AK + (q >> 1) * 8;
    int b_sel = (wn + (q >> 1) * 8 + rr) * AK + (q & 1) * 8;

    int arow = tid >> 2;            // 0..63
    int akg  = (tid & 3) * 8;
    bool aok = (bm + arow) < N_NODES;
    const float* abase = x + (size_t)(aok ? bm + arow : 0) * F_IN + akg;

    float acc[2][4][4] = {};
    float4 pf0, pf1;

    pf0 = aok ? *(const float4*)(abase)     : make_float4(0.f, 0.f, 0.f, 0.f);
    pf1 = aok ? *(const float4*)(abase + 4) : make_float4(0.f, 0.f, 0.f, 0.f);
#pragma unroll
    for (int h = 0; h < 2; h++) {   // B chunk 0: 128 rows x 32k
        int id = tid + h * 256;
        int row = id >> 2, kg = (id & 3) * 8;
        cp16(&Bs[0 * 128 * AK + row * AK + kg],
             g_w1t + (size_t)(bn + row) * F_IN + kg);
    }
    CP_COMMIT();

    const int nchunk = F_IN / 32;   // 16
    for (int c = 0; c < nchunk; c++) {
        int buf = c & 1;
        {   // STS A(c)
            __nv_bfloat162 p[4];
            p[0] = __floats2bfloat162_rn(pf0.x, pf0.y);
            p[1] = __floats2bfloat162_rn(pf0.z, pf0.w);
            p[2] = __floats2bfloat162_rn(pf1.x, pf1.y);
            p[3] = __floats2bfloat162_rn(pf1.z, pf1.w);
            *(uint4*)&As[buf * 64 * AK + arow * AK + akg] = *(uint4*)p;
        }
        if (c + 1 < nchunk) {
            int k0 = (c + 1) * 32;
            pf0 = aok ? *(const float4*)(abase + k0)     : make_float4(0.f, 0.f, 0.f, 0.f);
            pf1 = aok ? *(const float4*)(abase + k0 + 4) : make_float4(0.f, 0.f, 0.f, 0.f);
        }
        asm volatile("cp.async.wait_group 0;");
        __syncthreads();
        if (c + 1 < nchunk) {
            int k0 = (c + 1) * 32;
#pragma unroll
            for (int h = 0; h < 2; h++) {
                int id = tid + h * 256;
                int row = id >> 2, kg = (id & 3) * 8;
                cp16(&Bs[(1 - buf) * 128 * AK + row * AK + kg],
                     g_w1t + (size_t)(bn + row) * F_IN + k0 + kg);
            }
            CP_COMMIT();
        }
        const __nv_bfloat16* A = As + buf * 64 * AK;
        const __nv_bfloat16* B = Bs + buf * 128 * AK;
#pragma unroll
        for (int kk = 0; kk < 32; kk += 16) {
            unsigned a[2][4];
#pragma unroll
            for (int mt = 0; mt < 2; mt++)
                ldsm_x4(a[mt][0], a[mt][1], a[mt][2], a[mt][3],
                        A + a_sel + mt * 16 * AK + kk);
#pragma unroll
            for (int ntp = 0; ntp < 2; ntp++) {
                unsigned b0, b1, b2, b3;
                ldsm_x4(b0, b1, b2, b3, B + b_sel + ntp * 16 * AK + kk);
                mma16816(acc[0][2 * ntp],     a[0], b0, b1);
                mma16816(acc[1][2 * ntp],     a[1], b0, b1);
                mma16816(acc[0][2 * ntp + 1], a[0], b2, b3);
                mma16816(acc[1][2 * ntp + 1], a[1], b2, b3);
            }
        }
    }
#pragma unroll
    for (int mt = 0; mt < 2; mt++) {
        int r0 = bm + wm + mt * 16 + g;
#pragma unroll
        for (int nt = 0; nt < 4; nt++) {
            int c0 = bn + wn + nt * 8 + 2 * tg;
            if (r0 < N_NODES) {
                __nv_fp8x2_storage_t p = __nv_cvt_float2_to_fp8x2(
                    make_float2(acc[mt][nt][0], acc[mt][nt][1]),
                    __NV_SATFINITE, __NV_E4M3);
                *(unsigned short*)&g_h1f8[(size_t)r0 * F_HID + c0] = p;
            }
            if (r0 + 8 < N_NODES) {
                __nv_fp8x2_storage_t p = __nv_cvt_float2_to_fp8x2(
                    make_float2(acc[mt][nt][2], acc[mt][nt][3]),
                    __NV_SATFINITE, __NV_E4M3);
                *(unsigned short*)&g_h1f8[(size_t)(r0 + 8) * F_HID + c0] = p;
            }
        }
    }
}
#define G1D_SMEM ((2 * 64 + 2 * 128) * AK * (int)sizeof(__nv_bfloat16))

// ---------------- layer-1 aggregation: fp8 gather, half2 acc ---------------
__device__ __forceinline__ void acc4h(__half2* acc, uint2 v, __half2 nrm2) {
    const unsigned short* q = (const unsigned short*)&v;
#pragma unroll
    for (int i = 0; i < 4; i++) {
        __half2_raw hr = __nv_cvt_fp8x2_to_halfraw2((__nv_fp8x2_storage_t)q[i],
                                                    __NV_E4M3);
        acc[i] = __hfma2(*(__half2*)&hr, nrm2, acc[i]);
    }
}

__global__ __launch_bounds__(256) void k_agg1(const float* __restrict__ b1) {
    int node = (blockIdx.x * blockDim.x + threadIdx.x) >> 5;
    int lane = threadIdx.x & 31;
    if (node >= N_NODES) return;
    int beg = g_rowptr[node], end = g_rowptr[node + 1];
    float dinv_d = g_dinv[node];
    const uint2* hb = (const uint2*)g_h1f8;

    __half2 acc[4] = {__half2{__half(0.f), __half(0.f)},
                      __half2{__half(0.f), __half(0.f)},
                      __half2{__half(0.f), __half(0.f)},
                      __half2{__half(0.f), __half(0.f)}};
    int e = beg;
    for (; e + 4 <= end; e += 4) {
        int s0 = g_csrc[e], s1 = g_csrc[e + 1], s2 = g_csrc[e + 2], s3 = g_csrc[e + 3];
        __half2 n0 = __float2half2_rn(g_dinv[s0] * dinv_d);
        __half2 n1 = __float2half2_rn(g_dinv[s1] * dinv_d);
        __half2 n2 = __float2half2_rn(g_dinv[s2] * dinv_d);
        __half2 n3 = __float2half2_rn(g_dinv[s3] * dinv_d);
        uint2 v0 = hb[(size_t)s0 * 32 + lane];
        uint2 v1 = hb[(size_t)s1 * 32 + lane];
        uint2 v2 = hb[(size_t)s2 * 32 + lane];
        uint2 v3 = hb[(size_t)s3 * 32 + lane];
        acc4h(acc, v0, n0);
        acc4h(acc, v1, n1);
        acc4h(acc, v2, n2);
        acc4h(acc, v3, n3);
    }
    for (; e < end; e++) {
        int s0 = g_csrc[e];
        uint2 v = hb[(size_t)s0 * 32 + lane];
        acc4h(acc, v, __float2half2_rn(g_dinv[s0] * dinv_d));
    }
    {   // self loop
        uint2 v = hb[(size_t)node * 32 + lane];
        acc4h(acc, v, __float2half2_rn(dinv_d * dinv_d));
    }
    float2 f0 = __half22float2(acc[0]);
    float2 f1 = __half22float2(acc[1]);
    float2 f2 = __half22float2(acc[2]);
    float2 f3 = __half22float2(acc[3]);
    float4 bv0 = *((const float4*)b1 + lane * 2);
    float4 bv1 = *((const float4*)b1 + lane * 2 + 1);
    float r[8];
    r[0] = fmaxf(f0.x + bv0.x, 0.f); r[1] = fmaxf(f0.y + bv0.y, 0.f);
    r[2] = fmaxf(f1.x + bv0.z, 0.f); r[3] = fmaxf(f1.y + bv0.w, 0.f);
    r[4] = fmaxf(f2.x + bv1.x, 0.f); r[5] = fmaxf(f2.y + bv1.y, 0.f);
    r[6] = fmaxf(f3.x + bv1.z, 0.f); r[7] = fmaxf(f3.y + bv1.w, 0.f);
    __nv_bfloat162 p[4];
    p[0] = __floats2bfloat162_rn(r[0], r[1]);
    p[1] = __floats2bfloat162_rn(r[2], r[3]);
    p[2] = __floats2bfloat162_rn(r[4], r[5]);
    p[3] = __floats2bfloat162_rn(r[6], r[7]);
    ((uint4*)g_a1b)[(size_t)node * 32 + lane] = *(uint4*)p;
}

// ---------------- GEMM2: h2b = a1b @ W2 (bf16 mma, 128x64 tile) ------------
__global__ __launch_bounds__(256) void k_gemm2t() {
    __shared__ __align__(16) __nv_bfloat16 As[2][128 * AK];
    __shared__ __align__(16) __nv_bfloat16 Bs[2][64 * AK];
    int tid = threadIdx.x;
    int bm = blockIdx.x * 128;
    int wid = tid >> 5, lane = tid & 31;
    int wm = (wid & 3) * 32, wn = (wid >> 2) * 32;
    int g = lane >> 2, tg = lane & 3;

    float acc[2][4][4] = {};

#define G2_ISSUE(buf, k0)                                                     \
    {                                                                         \
        _Pragma("unroll")                                                     \
        for (int h = 0; h < 2; h++) {                                         \
            int id = tid + h * 256;                                           \
            int row = id >> 2, kg = id & 3;                                   \
            int ar = bm + row;                                                \
            bool ok = ar < N_NODES;                                           \
            const void* ga = g_a1b + (size_t)(ok ? ar : 0) * F_HID + (k0) + kg * 8; \
            cp16z(&As[buf][row * AK + kg * 8], ga, ok);                       \
        }                                                                     \
        {                                                                     \
            int row = tid >> 2, kg = tid & 3;                                 \
            if (row < 64) {                                                   \
                const void* gb = g_w2t + (size_t)row * F_HID + (k0) + kg * 8; \
                cp16(&Bs[buf][row * AK + kg * 8], gb);                        \
            }                                                                 \
        }                                                                     \
        CP_COMMIT();                                                          \
    }

    G2_ISSUE(0, 0)
    const int nchunk = F_HID / 32;   // 8
    for (int c = 0; c < nchunk; c++) {
        if (c + 1 < nchunk) {
            G2_ISSUE((c + 1) & 1, (c + 1) * 32)
            asm volatile("cp.async.wait_group 1;");
        } else {
            asm volatile("cp.async.wait_group 0;");
        }
        __syncthreads();
        const __nv_bfloat16* A = As[c & 1];
        const __nv_bfloat16* B = Bs[c & 1];
#pragma unroll
        for (int kk = 0; kk < 32; kk += 16) {
            unsigned a[2][4];
#pragma unroll
            for (int mt = 0; mt < 2; mt++) {
                int r = wm + mt * 16 + g;
                a[mt][0] = *(const unsigned*)&A[r * AK + kk + 2 * tg];
                a[mt][1] = *(const unsigned*)&A[(r + 8) * AK + kk + 2 * tg];
                a[mt][2] = *(const unsigned*)&A[r * AK + kk + 2 * tg + 8];
                a[mt][3] = *(const unsigned*)&A[(r + 8) * AK + kk + 2 * tg + 8];
            }
#pragma unroll
            for (int nt = 0; nt < 4; nt++) {
                int n = wn + nt * 8 + g;
                unsigned b0 = *(const unsigned*)&B[n * AK + kk + 2 * tg];
                unsigned b1 = *(const unsigned*)&B[n * AK + kk + 2 * tg + 8];
                mma16816(acc[0][nt], a[0], b0, b1);
                mma16816(acc[1][nt], a[1], b0, b1);
            }
        }
        __syncthreads();
    }
#pragma unroll
    for (int mt = 0; mt < 2; mt++) {
        int r0 = bm + wm + mt * 16 + g;
#pragma unroll
        for (int nt = 0; nt < 4; nt++) {
            int c0 = wn + nt * 8 + 2 * tg;
            if (c0 + 1 < H2P) {
                if (r0 < N_NODES) {
                    __nv_bfloat162 p = __floats2bfloat162_rn(acc[mt][nt][0], acc[mt][nt][1]);
                    *(__nv_bfloat162*)&g_h2b[(size_t)r0 * H2P + c0] = p;
                }
                if (r0 + 8 < N_NODES) {
                    __nv_bfloat162 p = __floats2bfloat162_rn(acc[mt][nt][2], acc[mt][nt][3]);
                    *(__nv_bfloat162*)&g_h2b[(size_t)(r0 + 8) * H2P + c0] = p;
                }
            }
        }
    }
}

// ---------------- layer-2 aggregation + log_softmax, 4-edge unroll ---------
__global__ __launch_bounds__(256) void k_agg2final(const float* __restrict__ b2,
                                                   float* __restrict__ out) {
    int node = (blockIdx.x * blockDim.x + threadIdx.x) >> 5;
    int lane = threadIdx.x & 31;
    if (node >= N_NODES) return;
    int beg = g_rowptr[node], end = g_rowptr[node + 1];
    float dinv_d = g_dinv[node];
    bool act = lane < 21;
    int c0 = lane * 2, c1 = lane * 2 + 1;

    float acc0 = 0.f, acc1 = 0.f;
    int e = beg;
    for (; e + 4 <= end; e += 4) {
        int s0 = g_csrc[e], s1 = g_csrc[e + 1], s2 = g_csrc[e + 2], s3 = g_csrc[e + 3];
        float n0 = g_dinv[s0] * dinv_d, n1 = g_dinv[s1] * dinv_d;
        float n2 = g_dinv[s2] * dinv_d, n3 = g_dinv[s3] * dinv_d;
        if (act) {
            __nv_bfloat162 w0 = *(const __nv_bfloat162*)&g_h2b[(size_t)s0 * H2P + c0];
            __nv_bfloat162 w1 = *(const __nv_bfloat162*)&g_h2b[(size_t)s1 * H2P + c0];
            __nv_bfloat162 w2 = *(const __nv_bfloat162*)&g_h2b[(size_t)s2 * H2P + c0];
            __nv_bfloat162 w3 = *(const __nv_bfloat162*)&g_h2b[(size_t)s3 * H2P + c0];
            float2 f0 = __bfloat1622float2(w0);
            float2 f1 = __bfloat1622float2(w1);
            float2 f2 = __bfloat1622float2(w2);
            float2 f3 = __bfloat1622float2(w3);
            acc0 += n0 * f0.x + n1 * f1.x + n2 * f2.x + n3 * f3.x;
            acc1 += n0 * f0.y + n1 * f1.y + n2 * f2.y + n3 * f3.y;
        }
    }
    for (; e < end; e++) {
        int s = g_csrc[e];
        float nrm = g_dinv[s] * dinv_d;
        if (act) {
            __nv_bfloat162 v = *(const __nv_bfloat162*)&g_h2b[(size_t)s * H2P + c0];
            float2 f = __bfloat1622float2(v);
            acc0 += nrm * f.x;
            acc1 += nrm * f.y;
        }
    }
    {
        float ds = dinv_d * dinv_d;
        if (act) {
            __nv_bfloat162 v = *(const __nv_bfloat162*)&g_h2b[(size_t)node * H2P + c0];
            float2 f = __bfloat1622float2(v);
            acc0 += ds * f.x;
            acc1 += ds * f.y;
        }
    }
    float v0 = act ? acc0 + b2[c0] : -1e30f;
    float v1 = (lane < 20) ? acc1 + b2[c1] : -1e30f;
    float m = fmaxf(v0, v1);
#pragma unroll
    for (int o = 16; o; o >>= 1) m = fmaxf(m, __shfl_xor_sync(0xffffffffu, m, o));
    float e2 = 0.f;
    if (act) e2 += expf(v0 - m);
    if (lane < 20) e2 += expf(v1 - m);
#pragma unroll
    for (int o = 16; o; o >>= 1) e2 += __shfl_xor_sync(0xffffffffu, e2, o);
    float ls = m + logf(e2);
    size_t base = (size_t)node * N_CLASS;
    if (act) out[base + c0] = v0 - ls;
    if (lane < 20) out[base + c1] = v1 - ls;
}

// ---------------------------------------------------------------------------
extern "C" void kernel_launch(void* const* d_in, const int* in_sizes, int n_in,
                              void* d_out, int out_size) {
    const float* x  = (const float*)d_in[0];
    const void*  ei = d_in[1];
    const float* W1 = (const float*)d_in[2];
    const float* b1 = (const float*)d_in[3];
    const float* W2 = (const float*)d_in[4];
    const float* b2 = (const float*)d_in[5];
    float* out = (float*)d_out;

    static cudaStream_t s_side = nullptr;
    static cudaEvent_t  e_fork = nullptr, e_join = nullptr;
    if (!s_side) {
        cudaStreamCreateWithFlags(&s_side, cudaStreamNonBlocking);
        cudaEventCreateWithFlags(&e_fork, cudaEventDisableTiming);
        cudaEventCreateWithFlags(&e_join, cudaEventDisableTiming);
    }
    cudaFuncSetAttribute(k_gemm1d, cudaFuncAttributeMaxDynamicSharedMemorySize,
                         G1D_SMEM);

    cudaEventRecord(e_fork, 0);
    cudaStreamWaitEvent(s_side, e_fork, 0);

    // Submission order keeps the GEMM as kernel #4 (ncu -s window).
    k_wt<<<(F_IN * F_HID + 64 * F_HID + 255) / 256, 256>>>(W1, W2);       // 1 main
    k_deg_detect<<<(N_NODES + 255) / 256, 256, 0, s_side>>>(ei);          // 2 side
    k_count<<<(N_EDGES + 255) / 256, 256, 0, s_side>>>(ei);               // 3 side
    {
        dim3 g1(F_HID / 128, (N_NODES + 63) / 64);   // (2, 1563) n fastest
        k_gemm1d<<<g1, 256, G1D_SMEM>>>(x);                               // 4 main
    }
    k_scan1<<<SCAN_BLOCKS, 256, 0, s_side>>>();                           // 5 side
    k_scan2<<<1, 512, 0, s_side>>>();                                     // 6 side
    k_scan3<<<(N_NODES + 255) / 256, 256, 0, s_side>>>();                 // 7 side
    k_fill<<<(N_EDGES + 255) / 256, 256, 0, s_side>>>(ei);                // 8 side
    cudaEventRecord(e_join, s_side);
    cudaStreamWaitEvent(0, e_join, 0);

    k_agg1<<<(N_NODES * 32 + 255) / 256, 256>>>(b1);                      // 9
    k_gemm2t<<<(N_NODES + 127) / 128, 256>>>();                           // 10
    k_agg2final<<<(N_NODES * 32 + 255) / 256, 256>>>(b2, out);            // 11
}

// round 17
// speedup vs baseline: 1.0478x; 1.0478x over previous
#include <cuda_runtime.h>
#include <cuda_bf16.h>
#include <cuda_fp16.h>
#include <cuda_fp8.h>

#define N_NODES 100000
#define N_EDGES 3200000
#define F_IN    512
#define F_HID   256
#define N_CLASS 41
#define H2P     44                            // padded h2 row (bf16)
#define SCAN_BLOCKS ((N_NODES + 255) / 256)   // 391
#define AK 40   // smem k-stride in bf16 halves (32 data + 8 pad)

// ---------------- scratch (device globals; no allocation allowed) ----------
__device__ __nv_bfloat16 g_w1t[(size_t)F_HID * F_IN];      // W1^T [n][k] bf16
__device__ __nv_bfloat16 g_w2t[(size_t)64 * F_HID];        // W2^T padded [64][256]
__device__ unsigned char g_h1f8[(size_t)N_NODES * F_HID];  // x@W1 in fp8 e4m3
__device__ __nv_bfloat16 g_a1b[(size_t)N_NODES * F_HID];   // relu(agg+self+b1) bf16
__device__ __nv_bfloat16 g_h2b[(size_t)N_NODES * H2P];     // a1 @ W2 (bf16, padded)
__device__ int   g_deg[N_NODES];
__device__ float g_dinv[N_NODES];
__device__ int   g_rowptr[N_NODES + 1];
__device__ int   g_cursor[N_NODES];
__device__ int   g_bsum[SCAN_BLOCKS];
__device__ int   g_bsumx[SCAN_BLOCKS];
__device__ int   g_csrc[N_EDGES];
__device__ int   g_is64;

// ---------------- small helpers --------------------------------------------
__device__ __forceinline__ void cp16(void* s, const void* g) {
    unsigned sa = (unsigned)__cvta_generic_to_shared(s);
    asm volatile("cp.async.cg.shared.global [%0],[%1],16;" :: "r"(sa), "l"(g));
}
__device__ __forceinline__ void cp16z(void* s, const void* g, bool pred) {
    unsigned sa = (unsigned)__cvta_generic_to_shared(s);
    int sz = pred ? 16 : 0;
    asm volatile("cp.async.cg.shared.global [%0],[%1],16,%2;" :: "r"(sa), "l"(g), "r"(sz));
}
#define CP_COMMIT() asm volatile("cp.async.commit_group;")

__device__ __forceinline__ void mma16816(float c[4], const unsigned a[4],
                                         unsigned b0, unsigned b1) {
    asm volatile(
        "mma.sync.aligned.m16n8k16.row.col.f32.bf16.bf16.f32 "
        "{%0,%1,%2,%3},{%4,%5,%6,%7},{%8,%9},{%0,%1,%2,%3};"
        : "+f"(c[0]), "+f"(c[1]), "+f"(c[2]), "+f"(c[3])
        : "r"(a[0]), "r"(a[1]), "r"(a[2]), "r"(a[3]), "r"(b0), "r"(b1));
}

__device__ __forceinline__ void ldsm_x4(unsigned& r0, unsigned& r1,
                                        unsigned& r2, unsigned& r3,
                                        const void* p) {
    unsigned addr = (unsigned)__cvta_generic_to_shared(p);
    asm volatile("ldmatrix.sync.aligned.m8n8.x4.shared.b16 {%0,%1,%2,%3},[%4];"
                 : "=r"(r0), "=r"(r1), "=r"(r2), "=r"(r3) : "r"(addr));
}

// ---------------- deg init + parallel edge-dtype detection ------------------
__global__ void k_deg_detect(const void* __restrict__ ei) {
    int i = blockIdx.x * blockDim.x + threadIdx.x;
    if (i < N_NODES) g_deg[i] = 1;
    if (blockIdx.x == 0) {
        __shared__ int s_ok;
        if (threadIdx.x == 0) s_ok = 1;
        __syncthreads();
        if (threadIdx.x < 128) {
            long long v = ((const long long*)ei)[threadIdx.x];
            if (v < 0 || v >= N_NODES) atomicAnd(&s_ok, 0);
        }
        __syncthreads();
        if (threadIdx.x == 0) g_is64 = s_ok;
    }
}

__device__ __forceinline__ void load_edge(const void* __restrict__ ei, int e,
                                          int is64, int& s, int& d) {
    if (is64) {
        const long long* p = (const long long*)ei;
        s = (int)p[e];
        d = (int)p[N_EDGES + e];
    } else {
        const int* p = (const int*)ei;
        s = p[e];
        d = p[N_EDGES + e];
    }
}

__global__ void k_count(const void* __restrict__ ei) {
    int e = blockIdx.x * blockDim.x + threadIdx.x;
    if (e >= N_EDGES) return;
    int s, d;
    load_edge(ei, e, g_is64, s, d);
    if ((unsigned)d < N_NODES) atomicAdd(&g_deg[d], 1);
}

// ---------------- CSR build -------------------------------------------------
__global__ void k_scan1() {
    __shared__ int sh[256];
    int t = threadIdx.x;
    int i = blockIdx.x * 256 + t;
    int deg = (i < N_NODES) ? g_deg[i] : 1;
    if (i < N_NODES) g_dinv[i] = rsqrtf((float)deg);
    int v = (i < N_NODES) ? (deg - 1) : 0;
    sh[t] = v;
    __syncthreads();
#pragma unroll
    for (int off = 1; off < 256; off <<= 1) {
        int add = (t >= off) ? sh[t - off] : 0;
        __syncthreads();
        sh[t] += add;
        __syncthreads();
    }
    if (i < N_NODES) g_rowptr[i] = sh[t] - v;
    if (t == 255) g_bsum[blockIdx.x] = sh[t];
}
__global__ void k_scan2() {
    __shared__ int sh[512];
    int t = threadIdx.x;
    int v = (t < SCAN_BLOCKS) ? g_bsum[t] : 0;
    sh[t] = v;
    __syncthreads();
#pragma unroll
    for (int off = 1; off < 512; off <<= 1) {
        int add = (t >= off) ? sh[t - off] : 0;
        __syncthreads();
        sh[t] += add;
        __syncthreads();
    }
    if (t < SCAN_BLOCKS) g_bsumx[t] = sh[t] - v;
}
__global__ void k_scan3() {
    int i = blockIdx.x * blockDim.x + threadIdx.x;
    if (i < N_NODES) {
        int r = g_rowptr[i] + g_bsumx[i >> 8];
        g_rowptr[i] = r;
        g_cursor[i] = r;
    }
    if (i == 0)
        g_rowptr[N_NODES] = g_bsumx[SCAN_BLOCKS - 1] + g_bsum[SCAN_BLOCKS - 1];
}
__global__ void k_fill(const void* __restrict__ ei) {
    int e = blockIdx.x * blockDim.x + threadIdx.x;
    if (e >= N_EDGES) return;
    int s, d;
    load_edge(ei, e, g_is64, s, d);
    if ((unsigned)s >= N_NODES || (unsigned)d >= N_NODES) return;
    int pos = atomicAdd(&g_cursor[d], 1);
    g_csrc[pos] = s;
}

// ---------------- weight conversions (merged) --------------------------------
__global__ void k_wt(const float* __restrict__ W1, const float* __restrict__ W2) {
    int id = blockIdx.x * blockDim.x + threadIdx.x;
    if (id < F_IN * F_HID) {
        int n = id & (F_HID - 1), k = id >> 8;
        g_w1t[(size_t)n * F_IN + k] = __float2bfloat16(W1[(size_t)k * F_HID + n]);
    } else if (id < F_IN * F_HID + 64 * F_HID) {
        int id2 = id - F_IN * F_HID;
        int n = id2 & 63, k = id2 >> 6;
        float v = (n < N_CLASS) ? W2[(size_t)k * N_CLASS + n] : 0.f;
        g_w2t[(size_t)n * F_HID + k] = __float2bfloat16(v);
    }
}

// ---------------- GEMM1: 64x256 tile, ldmatrix, 3-deep B pipeline ----------
__global__ __launch_bounds__(256, 2) void k_gemm1c(const float* __restrict__ x) {
    extern __shared__ __align__(16) __nv_bfloat16 smem[];
    __nv_bfloat16* As = smem;                  // 2 bufs x 64*AK
    __nv_bfloat16* Bs = smem + 2 * 64 * AK;    // 3 bufs x 256*AK
    int tid = threadIdx.x;
    int bm = blockIdx.x * 64;
    int wid = tid >> 5, lane = tid & 31;
    int wm = (wid & 1) * 32, wn = (wid >> 1) * 64;
    int g = lane >> 2, tg = lane & 3;

    int q = lane >> 3, rr = lane & 7;
    int a_sel = (wm + (q & 1) * 8 + rr) * AK + (q >> 1) * 8;
    int b_sel = (wn + (q >> 1) * 8 + rr) * AK + (q & 1) * 8;

    int arow = tid >> 2;
    int akg  = (tid & 3) * 8;
    bool aok = (bm + arow) < N_NODES;
    const float* abase = x + (size_t)(aok ? bm + arow : 0) * F_IN + akg;

    float acc[2][8][4] = {};
    float4 pf0, pf1;

    // prologue: A chunk0 regs; B chunks 0 and 1 in flight (2 groups).
    pf0 = aok ? *(const float4*)(abase)     : make_float4(0.f, 0.f, 0.f, 0.f);
    pf1 = aok ? *(const float4*)(abase + 4) : make_float4(0.f, 0.f, 0.f, 0.f);
#pragma unroll
    for (int pc = 0; pc < 2; pc++) {
#pragma unroll
        for (int h = 0; h < 4; h++) {
            int id = tid + h * 256;
            int row = id >> 2, kg = (id & 3) * 8;
            cp16(&Bs[pc * 256 * AK + row * AK + kg],
                 g_w1t + (size_t)row * F_IN + pc * 32 + kg);
        }
        CP_COMMIT();
    }

    const int nchunk = F_IN / 32;   // 16
    int bbuf = 0;                    // B buffer index for chunk c (c % 3)
    for (int c = 0; c < nchunk; c++) {
        int abuf = c & 1;
        {   // STS A(c): safe, compute(c-2) (last reader) finished pre sync(c-1)
            __nv_bfloat162 p[4];
            p[0] = __floats2bfloat162_rn(pf0.x, pf0.y);
            p[1] = __floats2bfloat162_rn(pf0.z, pf0.w);
            p[2] = __floats2bfloat162_rn(pf1.x, pf1.y);
            p[3] = __floats2bfloat162_rn(pf1.z, pf1.w);
            *(uint4*)&As[abuf * 64 * AK + arow * AK + akg] = *(uint4*)p;
        }
        if (c + 1 < nchunk) {
            int k0 = (c + 1) * 32;
            pf0 = aok ? *(const float4*)(abase + k0)     : make_float4(0.f, 0.f, 0.f, 0.f);
            pf1 = aok ? *(const float4*)(abase + k0 + 4) : make_float4(0.f, 0.f, 0.f, 0.f);
        }
        // B(c) resident (wait all but newest group); B(c+1) may stay in flight.
        if (c + 1 < nchunk) {
            asm volatile("cp.async.wait_group 1;");
        } else {
            asm volatile("cp.async.wait_group 0;");
        }
        __syncthreads();
        // issue B(c+2) into buf (c+2)%3: last reader compute(c-1) done by sync(c)
        if (c + 2 < nchunk) {
            int k0 = (c + 2) * 32;
            int nb = bbuf + 2; if (nb >= 3) nb -= 3;
#pragma unroll
            for (int h = 0; h < 4; h++) {
                int id = tid + h * 256;
                int row = id >> 2, kg = (id & 3) * 8;
                cp16(&Bs[nb * 256 * AK + row * AK + kg],
                     g_w1t + (size_t)row * F_IN + k0 + kg);
            }
            CP_COMMIT();
        }
        const __nv_bfloat16* A = As + abuf * 64 * AK;
        const __nv_bfloat16* B = Bs + bbuf * 256 * AK;
#pragma unroll
        for (int kk = 0; kk < 32; kk += 16) {
            unsigned a[2][4];
#pragma unroll
            for (int mt = 0; mt < 2; mt++)
                ldsm_x4(a[mt][0], a[mt][1], a[mt][2], a[mt][3],
                        A + a_sel + mt * 16 * AK + kk);
#pragma unroll
            for (int ntp = 0; ntp < 4; ntp++) {
                unsigned b0, b1, b2, b3;
                ldsm_x4(b0, b1, b2, b3, B + b_sel + ntp * 16 * AK + kk);
                mma16816(acc[0][2 * ntp],     a[0], b0, b1);
                mma16816(acc[1][2 * ntp],     a[1], b0, b1);
                mma16816(acc[0][2 * ntp + 1], a[0], b2, b3);
                mma16816(acc[1][2 * ntp + 1], a[1], b2, b3);
            }
        }
        if (++bbuf == 3) bbuf = 0;
    }
#pragma unroll
    for (int mt = 0; mt < 2; mt++) {
        int r0 = bm + wm + mt * 16 + g;
#pragma unroll
        for (int nt = 0; nt < 8; nt++) {
            int c0 = wn + nt * 8 + 2 * tg;
            if (r0 < N_NODES) {
                __nv_fp8x2_storage_t p = __nv_cvt_float2_to_fp8x2(
                    make_float2(acc[mt][nt][0], acc[mt][nt][1]),
                    __NV_SATFINITE, __NV_E4M3);
                *(unsigned short*)&g_h1f8[(size_t)r0 * F_HID + c0] = p;
            }
            if (r0 + 8 < N_NODES) {
                __nv_fp8x2_storage_t p = __nv_cvt_float2_to_fp8x2(
                    make_float2(acc[mt][nt][2], acc[mt][nt][3]),
                    __NV_SATFINITE, __NV_E4M3);
                *(unsigned short*)&g_h1f8[(size_t)(r0 + 8) * F_HID + c0] = p;
            }
        }
    }
}
#define G1C_SMEM ((2 * 64 + 3 * 256) * AK * (int)sizeof(__nv_bfloat16))

// ---------------- layer-1 aggregation: fp8 gather, half2 acc ---------------
__device__ __forceinline__ void acc4h(__half2* acc, uint2 v, __half2 nrm2) {
    const unsigned short* q = (const unsigned short*)&v;
#pragma unroll
    for (int i = 0; i < 4; i++) {
        __half2_raw hr = __nv_cvt_fp8x2_to_halfraw2((__nv_fp8x2_storage_t)q[i],
                                                    __NV_E4M3);
        acc[i] = __hfma2(*(__half2*)&hr, nrm2, acc[i]);
    }
}

__global__ __launch_bounds__(256) void k_agg1(const float* __restrict__ b1) {
    int node = (blockIdx.x * blockDim.x + threadIdx.x) >> 5;
    int lane = threadIdx.x & 31;
    if (node >= N_NODES) return;
    int beg = g_rowptr[node], end = g_rowptr[node + 1];
    float dinv_d = g_dinv[node];
    const uint2* hb = (const uint2*)g_h1f8;

    __half2 acc[4] = {__half2{__half(0.f), __half(0.f)},
                      __half2{__half(0.f), __half(0.f)},
                      __half2{__half(0.f), __half(0.f)},
                      __half2{__half(0.f), __half(0.f)}};
    int e = beg;
    for (; e + 4 <= end; e += 4) {
        int s0 = g_csrc[e], s1 = g_csrc[e + 1], s2 = g_csrc[e + 2], s3 = g_csrc[e + 3];
        __half2 n0 = __float2half2_rn(g_dinv[s0] * dinv_d);
        __half2 n1 = __float2half2_rn(g_dinv[s1] * dinv_d);
        __half2 n2 = __float2half2_rn(g_dinv[s2] * dinv_d);
        __half2 n3 = __float2half2_rn(g_dinv[s3] * dinv_d);
        uint2 v0 = hb[(size_t)s0 * 32 + lane];
        uint2 v1 = hb[(size_t)s1 * 32 + lane];
        uint2 v2 = hb[(size_t)s2 * 32 + lane];
        uint2 v3 = hb[(size_t)s3 * 32 + lane];
        acc4h(acc, v0, n0);
        acc4h(acc, v1, n1);
        acc4h(acc, v2, n2);
        acc4h(acc, v3, n3);
    }
    for (; e < end; e++) {
        int s0 = g_csrc[e];
        uint2 v = hb[(size_t)s0 * 32 + lane];
        acc4h(acc, v, __float2half2_rn(g_dinv[s0] * dinv_d));
    }
    {   // self loop
        uint2 v = hb[(size_t)node * 32 + lane];
        acc4h(acc, v, __float2half2_rn(dinv_d * dinv_d));
    }
    float2 f0 = __half22float2(acc[0]);
    float2 f1 = __half22float2(acc[1]);
    float2 f2 = __half22float2(acc[2]);
    float2 f3 = __half22float2(acc[3]);
    float4 bv0 = *((const float4*)b1 + lane * 2);
    float4 bv1 = *((const float4*)b1 + lane * 2 + 1);
    float r[8];
    r[0] = fmaxf(f0.x + bv0.x, 0.f); r[1] = fmaxf(f0.y + bv0.y, 0.f);
    r[2] = fmaxf(f1.x + bv0.z, 0.f); r[3] = fmaxf(f1.y + bv0.w, 0.f);
    r[4] = fmaxf(f2.x + bv1.x, 0.f); r[5] = fmaxf(f2.y + bv1.y, 0.f);
    r[6] = fmaxf(f3.x + bv1.z, 0.f); r[7] = fmaxf(f3.y + bv1.w, 0.f);
    __nv_bfloat162 p[4];
    p[0] = __floats2bfloat162_rn(r[0], r[1]);
    p[1] = __floats2bfloat162_rn(r[2], r[3]);
    p[2] = __floats2bfloat162_rn(r[4], r[5]);
    p[3] = __floats2bfloat162_rn(r[6], r[7]);
    ((uint4*)g_a1b)[(size_t)node * 32 + lane] = *(uint4*)p;
}

// ---------------- GEMM2: h2b = a1b @ W2 (bf16 mma, 128x64 tile) ------------
__global__ __launch_bounds__(256) void k_gemm2t() {
    __shared__ __align__(16) __nv_bfloat16 As[2][128 * AK];
    __shared__ __align__(16) __nv_bfloat16 Bs[2][64 * AK];
    int tid = threadIdx.x;
    int bm = blockIdx.x * 128;
    int wid = tid >> 5, lane = tid & 31;
    int wm = (wid & 3) * 32, wn = (wid >> 2) * 32;
    int g = lane >> 2, tg = lane & 3;

    float acc[2][4][4] = {};

#define G2_ISSUE(buf, k0)                                                     \
    {                                                                         \
        _Pragma("unroll")                                                     \
        for (int h = 0; h < 2; h++) {                                         \
            int id = tid + h * 256;                                           \
            int row = id >> 2, kg = id & 3;                                   \
            int ar = bm + row;                                                \
            bool ok = ar < N_NODES;                                           \
            const void* ga = g_a1b + (size_t)(ok ? ar : 0) * F_HID + (k0) + kg * 8; \
            cp16z(&As[buf][row * AK + kg * 8], ga, ok);                       \
        }                                                                     \
        {                                                                     \
            int row = tid >> 2, kg = tid & 3;                                 \
            if (row < 64) {                                                   \
                const void* gb = g_w2t + (size_t)row * F_HID + (k0) + kg * 8; \
                cp16(&Bs[buf][row * AK + kg * 8], gb);                        \
            }                                                                 \
        }                                                                     \
        CP_COMMIT();                                                          \
    }

    G2_ISSUE(0, 0)
    const int nchunk = F_HID / 32;   // 8
    for (int c = 0; c < nchunk; c++) {
        if (c + 1 < nchunk) {
            G2_ISSUE((c + 1) & 1, (c + 1) * 32)
            asm volatile("cp.async.wait_group 1;");
        } else {
            asm volatile("cp.async.wait_group 0;");
        }
        __syncthreads();
        const __nv_bfloat16* A = As[c & 1];
        const __nv_bfloat16* B = Bs[c & 1];
#pragma unroll
        for (int kk = 0; kk < 32; kk += 16) {
            unsigned a[2][4];
#pragma unroll
            for (int mt = 0; mt < 2; mt++) {
                int r = wm + mt * 16 + g;
                a[mt][0] = *(const unsigned*)&A[r * AK + kk + 2 * tg];
                a[mt][1] = *(const unsigned*)&A[(r + 8) * AK + kk + 2 * tg];
                a[mt][2] = *(const unsigned*)&A[r * AK + kk + 2 * tg + 8];
                a[mt][3] = *(const unsigned*)&A[(r + 8) * AK + kk + 2 * tg + 8];
            }
#pragma unroll
            for (int nt = 0; nt < 4; nt++) {
                int n = wn + nt * 8 + g;
                unsigned b0 = *(const unsigned*)&B[n * AK + kk + 2 * tg];
                unsigned b1 = *(const unsigned*)&B[n * AK + kk + 2 * tg + 8];
                mma16816(acc[0][nt], a[0], b0, b1);
                mma16816(acc[1][nt], a[1], b0, b1);
            }
        }
        __syncthreads();
    }
#pragma unroll
    for (int mt = 0; mt < 2; mt++) {
        int r0 = bm + wm + mt * 16 + g;
#pragma unroll
        for (int nt = 0; nt < 4; nt++) {
            int c0 = wn + nt * 8 + 2 * tg;
            if (c0 + 1 < H2P) {
                if (r0 < N_NODES) {
                    __nv_bfloat162 p = __floats2bfloat162_rn(acc[mt][nt][0], acc[mt][nt][1]);
                    *(__nv_bfloat162*)&g_h2b[(size_t)r0 * H2P + c0] = p;
                }
                if (r0 + 8 < N_NODES) {
                    __nv_bfloat162 p = __floats2bfloat162_rn(acc[mt][nt][2], acc[mt][nt][3]);
                    *(__nv_bfloat162*)&g_h2b[(size_t)(r0 + 8) * H2P + c0] = p;
                }
            }
        }
    }
}

// ---------------- layer-2 aggregation + log_softmax ------------------------
__global__ __launch_bounds__(256) void k_agg2final(const float* __restrict__ b2,
                                                   float* __restrict__ out) {
    int node = (blockIdx.x * blockDim.x + threadIdx.x) >> 5;
    int lane = threadIdx.x & 31;
    if (node >= N_NODES) return;
    int beg = g_rowptr[node], end = g_rowptr[node + 1];
    float dinv_d = g_dinv[node];
    bool act = lane < 21;
    int c0 = lane * 2, c1 = lane * 2 + 1;

    float acc0 = 0.f, acc1 = 0.f;
    for (int e = beg; e < end; e++) {
        int s = g_csrc[e];
        float nrm = g_dinv[s] * dinv_d;
        if (act) {
            __nv_bfloat162 v = *(const __nv_bfloat162*)&g_h2b[(size_t)s * H2P + c0];
            float2 f = __bfloat1622float2(v);
            acc0 += nrm * f.x;
            acc1 += nrm * f.y;
        }
    }
    {
        float ds = dinv_d * dinv_d;
        if (act) {
            __nv_bfloat162 v = *(const __nv_bfloat162*)&g_h2b[(size_t)node * H2P + c0];
            float2 f = __bfloat1622float2(v);
            acc0 += ds * f.x;
            acc1 += ds * f.y;
        }
    }
    float v0 = act ? acc0 + b2[c0] : -1e30f;
    float v1 = (lane < 20) ? acc1 + b2[c1] : -1e30f;
    float m = fmaxf(v0, v1);
#pragma unroll
    for (int o = 16; o; o >>= 1) m = fmaxf(m, __shfl_xor_sync(0xffffffffu, m, o));
    float e2 = 0.f;
    if (act) e2 += expf(v0 - m);
    if (lane < 20) e2 += expf(v1 - m);
#pragma unroll
    for (int o = 16; o; o >>= 1) e2 += __shfl_xor_sync(0xffffffffu, e2, o);
    float ls = m + logf(e2);
    size_t base = (size_t)node * N_CLASS;
    if (act) out[base + c0] = v0 - ls;
    if (lane < 20) out[base + c1] = v1 - ls;
}

// ---------------------------------------------------------------------------
extern "C" void kernel_launch(void* const* d_in, const int* in_sizes, int n_in,
                              void* d_out, int out_size) {
    const float* x  = (const float*)d_in[0];
    const void*  ei = d_in[1];
    const float* W1 = (const float*)d_in[2];
    const float* b1 = (const float*)d_in[3];
    const float* W2 = (const float*)d_in[4];
    const float* b2 = (const float*)d_in[5];
    float* out = (float*)d_out;

    static cudaStream_t s_side = nullptr;
    static cudaEvent_t  e_fork = nullptr, e_join = nullptr;
    if (!s_side) {
        cudaStreamCreateWithFlags(&s_side, cudaStreamNonBlocking);
        cudaEventCreateWithFlags(&e_fork, cudaEventDisableTiming);
        cudaEventCreateWithFlags(&e_join, cudaEventDisableTiming);
    }
    cudaFuncSetAttribute(k_gemm1c, cudaFuncAttributeMaxDynamicSharedMemorySize,
                         G1C_SMEM);

    cudaEventRecord(e_fork, 0);
    cudaStreamWaitEvent(s_side, e_fork, 0);

    // Submission order keeps the GEMM as kernel #4 (ncu -s window).
    k_wt<<<(F_IN * F_HID + 64 * F_HID + 255) / 256, 256>>>(W1, W2);       // 1 main
    k_deg_detect<<<(N_NODES + 255) / 256, 256, 0, s_side>>>(ei);          // 2 side
    k_count<<<(N_EDGES + 255) / 256, 256, 0, s_side>>>(ei);               // 3 side
    k_gemm1c<<<(N_NODES + 63) / 64, 256, G1C_SMEM>>>(x);                  // 4 main
    k_scan1<<<SCAN_BLOCKS, 256, 0, s_side>>>();                           // 5 side
    k_scan2<<<1, 512, 0, s_side>>>();                                     // 6 side
    k_scan3<<<(N_NODES + 255) / 256, 256, 0, s_side>>>();                 // 7 side
    k_fill<<<(N_EDGES + 255) / 256, 256, 0, s_side>>>(ei);                // 8 side
    cudaEventRecord(e_join, s_side);
    cudaStreamWaitEvent(0, e_join, 0);

    k_agg1<<<(N_NODES * 32 + 255) / 256, 256>>>(b1);                      // 9
    k_gemm2t<<<(N_NODES + 127) / 128, 256>>>();                           // 10
    k_agg2final<<<(N_NODES * 32 + 255) / 256, 256>>>(b2, out);            // 11
}